// round 4
// baseline (speedup 1.0000x reference)
#include <cuda_runtime.h>
#include <cuda_bf16.h>

#define N_ 64
#define T_ 2048
#define D_ 256

// Scratch (no allocs allowed)
__device__ float    g_energy[N_ * T_];
__device__ unsigned g_maxbits[N_];
__device__ float    g_Z[N_];

// Order-preserving float->uint encoding (monotone for atomicMax)
__device__ __forceinline__ unsigned fenc(float f) {
    unsigned u = __float_as_uint(f);
    return (u & 0x80000000u) ? ~u : (u | 0x80000000u);
}
__device__ __forceinline__ float fdec(unsigned e) {
    return __uint_as_float((e & 0x80000000u) ? (e ^ 0x80000000u) : ~e);
}

// Robust lens decode: values are in [1, T]. If stored as int64 (little-endian),
// the high word of element 0 (int32 view index 1) is 0; if int32, it's >= 1.
__device__ __forceinline__ int get_len(const int* __restrict__ lens32, int n) {
    const bool is64 = (lens32[1] == 0);
    return is64 ? lens32[2 * n] : lens32[n];
}

// ---------------------------------------------------------------------------
// K0: reset per-row max/Z, zero context, zero-fill attn (masked tail stays 0)
// Grid: 512 x 256 covers N*T = 131072 elements.
// ---------------------------------------------------------------------------
__global__ void k_init(float* __restrict__ ctx, float* __restrict__ attn) {
    const int i = blockIdx.x * blockDim.x + threadIdx.x;
    if (i < N_) { g_maxbits[i] = 0u; g_Z[i] = 0.0f; }
    if (i < N_ * D_) ctx[i] = 0.0f;
    if (i < N_ * T_) attn[i] = 0.0f;
}

// ---------------------------------------------------------------------------
// K1: energies e[n,t] = <key[n,t,:], query[n,:]> for t < lens[n]; row max.
// Grid: (T/64, N), 256 threads. 8 lanes per row => each lane does 8 unrolled
// float4 loads (independent, MLP=8), 3-level shfl reduce.
// ---------------------------------------------------------------------------
__global__ void k_energy(const float* __restrict__ q,
                         const float* __restrict__ key,
                         const int* __restrict__ lens32) {
    const int n   = blockIdx.y;
    const int len = get_len(lens32, n);
    const int t0  = blockIdx.x * 64;
    if (t0 >= len) return;                    // skip fully-masked tiles

    __shared__ float4   qs4[D_ / 4];
    __shared__ unsigned bmax;
    const int tid = threadIdx.x;
    if (tid == 0) bmax = 0u;
    if (tid < 64) qs4[tid] = ((const float4*)(q + n * D_))[tid];
    __syncthreads();

    const int warp = tid >> 5, lane = tid & 31;
    const int sub  = lane >> 3;               // row within 4-row group
    const int sl   = lane & 7;                // lane within row (8 lanes/row)

    unsigned lmax = 0u;
    #pragma unroll
    for (int iter = 0; iter < 2; ++iter) {
        const int t = t0 + warp * 8 + iter * 4 + sub;
        float s = 0.0f;
        if (t < len) {
            const float4* krow = (const float4*)(key + ((size_t)n * T_ + t) * D_);
            #pragma unroll
            for (int k = 0; k < 8; ++k) {     // 8 independent 16B loads in flight
                const float4 kv = krow[sl + k * 8];
                const float4 qv = qs4[sl + k * 8];
                s += kv.x * qv.x + kv.y * qv.y + kv.z * qv.z + kv.w * qv.w;
            }
        }
        s += __shfl_xor_sync(0xffffffff, s, 4);
        s += __shfl_xor_sync(0xffffffff, s, 2);
        s += __shfl_xor_sync(0xffffffff, s, 1);
        if (sl == 0 && t < len) {
            g_energy[n * T_ + t] = s;
            const unsigned e = fenc(s);
            if (e > lmax) lmax = e;
        }
    }
    if (lmax) atomicMax(&bmax, lmax);
    __syncthreads();
    if (tid == 0 && bmax) atomicMax(&g_maxbits[n], bmax);
}

// ---------------------------------------------------------------------------
// K2: partial softmax denominator Z[n] = sum_t exp(e - m). Grid (4, N) x 256:
// each CTA sums a 512-wide t-slice of the L2-hot energy buffer, atomicAdd.
// ---------------------------------------------------------------------------
__global__ void k_zsum(const int* __restrict__ lens32) {
    const int n   = blockIdx.y;
    const int len = get_len(lens32, n);
    const int t0  = blockIdx.x * 512;
    if (t0 >= len) return;
    const int tend = min(t0 + 512, len);
    const float m  = fdec(g_maxbits[n]);
    const int tid  = threadIdx.x;

    float s = 0.0f;
    for (int t = t0 + tid; t < tend; t += 256)
        s += __expf(g_energy[n * T_ + t] - m);

    #pragma unroll
    for (int o = 16; o; o >>= 1) s += __shfl_xor_sync(0xffffffff, s, o);

    __shared__ float red[8];
    if ((tid & 31) == 0) red[tid >> 5] = s;
    __syncthreads();
    if (tid == 0) {
        float tot = 0.0f;
        #pragma unroll
        for (int w = 0; w < 8; ++w) tot += red[w];
        atomicAdd(&g_Z[n], tot);
    }
}

// ---------------------------------------------------------------------------
// K3: p = exp(e-m)/Z (written to attn), context += p * V. Tile = 64 t-rows.
// 256 threads: d4 = tid&63 (float4 column), rg = tid>>6 (4 row groups),
// unroll 4 => 4 independent 16B loads in flight. Grid: (T/64, N).
// ---------------------------------------------------------------------------
__global__ void k_context(const float* __restrict__ val,
                          const int* __restrict__ lens32,
                          float* __restrict__ attn,
                          float* __restrict__ ctx) {
    const int n   = blockIdx.y;
    const int len = get_len(lens32, n);
    const int t0  = blockIdx.x * 64;
    if (t0 >= len) return;
    const int cnt = min(64, len - t0);
    const int tid = threadIdx.x;
    const int d4  = tid & 63;                 // float4 column index
    const int rg  = tid >> 6;                 // row group 0..3

    __shared__ float  ps[64];
    __shared__ float4 red[4][64];

    if (tid < 64) {
        float p = 0.0f;
        if (tid < cnt) {
            const float m = fdec(g_maxbits[n]);
            const float invZ = 1.0f / g_Z[n];
            p = __expf(g_energy[n * T_ + t0 + tid] - m) * invZ;
            attn[n * T_ + t0 + tid] = p;      // tail beyond len stays 0 from k_init
        }
        ps[tid] = p;
    }
    __syncthreads();

    const float4* v4 = (const float4*)(val + ((size_t)n * T_ + t0) * D_) + d4;
    float4 acc = make_float4(0.f, 0.f, 0.f, 0.f);
    #pragma unroll 4
    for (int i = rg; i < cnt; i += 4) {       // independent loads across unrolled iters
        const float  p = ps[i];
        const float4 v = v4[(size_t)i * 64];
        acc.x += p * v.x; acc.y += p * v.y; acc.z += p * v.z; acc.w += p * v.w;
    }

    red[rg][d4] = acc;
    __syncthreads();
    if (rg == 0) {
        const float4 a = red[0][d4], b = red[1][d4], c = red[2][d4], e = red[3][d4];
        float* dst = &ctx[n * D_ + d4 * 4];
        atomicAdd(dst + 0, a.x + b.x + c.x + e.x);
        atomicAdd(dst + 1, a.y + b.y + c.y + e.y);
        atomicAdd(dst + 2, a.z + b.z + c.z + e.z);
        atomicAdd(dst + 3, a.w + b.w + c.w + e.w);
    }
}

// ---------------------------------------------------------------------------
extern "C" void kernel_launch(void* const* d_in, const int* in_sizes, int n_in,
                              void* d_out, int out_size) {
    const float* q    = (const float*)d_in[0];
    const float* key  = (const float*)d_in[1];
    const float* val  = (const float*)d_in[2];
    const int*   lens = (const int*)d_in[3];
    float* ctx  = (float*)d_out;            // first tuple element: [N, D]
    float* attn = (float*)d_out + N_ * D_;  // second tuple element: [N, T]

    k_init<<<512, 256>>>(ctx, attn);
    k_energy<<<dim3(T_ / 64, N_), 256>>>(q, key, lens);
    k_zsum<<<dim3(4, N_), 256>>>(lens);
    k_context<<<dim3(T_ / 64, N_), 256>>>(val, lens, attn, ctx);
}

// round 5
// speedup vs baseline: 1.0344x; 1.0344x over previous
#include <cuda_runtime.h>
#include <cuda_bf16.h>
#include <math_constants.h>

#define N_ 64
#define T_ 2048
#define D_ 256
#define ETILE 64
#define NTILES (T_ / ETILE)   // 32 energy tiles per n

// Scratch (no allocs allowed)
__device__ float    g_energy[N_ * T_];
__device__ unsigned g_maxbits[N_];
__device__ float    g_Z[N_];
__device__ float    g_tml[N_ * NTILES];   // per-tile local max
__device__ float    g_tsl[N_ * NTILES];   // per-tile sum exp(e - ml)

// Order-preserving float->uint encoding (monotone for atomicMax)
__device__ __forceinline__ unsigned fenc(float f) {
    unsigned u = __float_as_uint(f);
    return (u & 0x80000000u) ? ~u : (u | 0x80000000u);
}
__device__ __forceinline__ float fdec(unsigned e) {
    return __uint_as_float((e & 0x80000000u) ? (e ^ 0x80000000u) : ~e);
}

// Robust lens decode: values are in [1, T]. If stored as int64 (little-endian),
// the high word of element 0 (int32 view index 1) is 0; if int32, it's >= 1.
__device__ __forceinline__ int get_len(const int* __restrict__ lens32, int n) {
    const bool is64 = (lens32[1] == 0);
    return is64 ? lens32[2 * n] : lens32[n];
}

// ---------------------------------------------------------------------------
// K0: zero ctx, reset maxbits and per-tile sums. Grid: 64 x 256.
// ---------------------------------------------------------------------------
__global__ void k_init(float* __restrict__ ctx) {
    const int i = blockIdx.x * blockDim.x + threadIdx.x;
    if (i < N_) g_maxbits[i] = 0u;
    if (i < N_ * NTILES) g_tsl[i] = 0.0f;
    if (i < N_ * D_) ctx[i] = 0.0f;
}

// ---------------------------------------------------------------------------
// K1: e[n,t] = <key[n,t,:], q[n,:]> for t < len; store e; per-tile (ml, sl);
// one atomicMax per CTA for global max. Grid (T/64, N) x 256.
// 8 lanes per row: 8 independent float4 loads in flight per lane.
// ---------------------------------------------------------------------------
__global__ void k_energy(const float* __restrict__ q,
                         const float* __restrict__ key,
                         const int* __restrict__ lens32) {
    const int n   = blockIdx.y;
    const int len = get_len(lens32, n);
    const int t0  = blockIdx.x * ETILE;
    if (t0 >= len) return;                    // fully-masked tile (sl stays 0)

    __shared__ float4 qs4[D_ / 4];
    __shared__ float  es[ETILE];
    const int tid = threadIdx.x;
    if (tid < 64) qs4[tid] = ((const float4*)(q + n * D_))[tid];
    __syncthreads();

    const int warp = tid >> 5, lane = tid & 31;
    const int sub  = lane >> 3;               // row within 4-row group
    const int sl   = lane & 7;                // lane within row (8 lanes/row)

    #pragma unroll
    for (int iter = 0; iter < 2; ++iter) {
        const int r = warp * 8 + iter * 4 + sub;   // row in tile [0,64)
        const int t = t0 + r;
        float s = 0.0f;
        if (t < len) {
            const float4* krow = (const float4*)(key + ((size_t)n * T_ + t) * D_);
            #pragma unroll
            for (int k = 0; k < 8; ++k) {     // 8 independent 16B loads in flight
                const float4 kv = krow[sl + k * 8];
                const float4 qv = qs4[sl + k * 8];
                s += kv.x * qv.x + kv.y * qv.y + kv.z * qv.z + kv.w * qv.w;
            }
        }
        s += __shfl_xor_sync(0xffffffff, s, 4);
        s += __shfl_xor_sync(0xffffffff, s, 2);
        s += __shfl_xor_sync(0xffffffff, s, 1);
        if (sl == 0) {
            if (t < len) {
                g_energy[n * T_ + t] = s;
                es[r] = s;
            } else {
                es[r] = -CUDART_INF_F;        // exp(-inf - m) == 0, safe
            }
        }
    }
    __syncthreads();

    // CTA epilogue: warp 0 reduces the 64 row-energies to (ml, sl)
    if (warp == 0) {
        const float v0 = es[lane], v1 = es[lane + 32];
        float ml = fmaxf(v0, v1);
        #pragma unroll
        for (int o = 16; o; o >>= 1)
            ml = fmaxf(ml, __shfl_xor_sync(0xffffffff, ml, o));
        float ssum = __expf(v0 - ml) + __expf(v1 - ml);
        #pragma unroll
        for (int o = 16; o; o >>= 1)
            ssum += __shfl_xor_sync(0xffffffff, ssum, o);
        if (lane == 0) {
            const int ti = n * NTILES + blockIdx.x;
            g_tml[ti] = ml;
            g_tsl[ti] = ssum;
            atomicMax(&g_maxbits[n], fenc(ml));
        }
    }
}

// ---------------------------------------------------------------------------
// K2: combine per-tile sums: Z[n] = sum_tiles sl * exp(ml - m). Grid N x 32.
// ---------------------------------------------------------------------------
__global__ void k_combine() {
    const int n    = blockIdx.x;
    const int lane = threadIdx.x;
    const float m  = fdec(g_maxbits[n]);
    const float sl = g_tsl[n * NTILES + lane];
    float c = (sl > 0.0f) ? sl * __expf(g_tml[n * NTILES + lane] - m) : 0.0f;
    #pragma unroll
    for (int o = 16; o; o >>= 1) c += __shfl_xor_sync(0xffffffff, c, o);
    if (lane == 0) g_Z[n] = c;
}

// ---------------------------------------------------------------------------
// K3: p = exp(e-m)/Z -> attn (zeros past len); ctx += p * V. 128-row tiles.
// 256 threads: d4 = tid&63 (float4 col), rg = tid>>6 (4 row groups), unroll 8.
// Grid: (T/128, N).
// ---------------------------------------------------------------------------
__global__ void k_context(const float* __restrict__ val,
                          const int* __restrict__ lens32,
                          float* __restrict__ attn,
                          float* __restrict__ ctx) {
    const int n   = blockIdx.y;
    const int len = get_len(lens32, n);
    const int t0  = blockIdx.x * 128;
    const int tid = threadIdx.x;

    if (t0 >= len) {                          // masked tile: just zero attn
        if (tid < 128) attn[n * T_ + t0 + tid] = 0.0f;
        return;
    }
    const int cnt = min(128, len - t0);
    const int d4  = tid & 63;
    const int rg  = tid >> 6;

    __shared__ float  ps[128];
    __shared__ float4 red[4][64];

    if (tid < 128) {
        float p = 0.0f;
        if (tid < cnt) {
            const float m    = fdec(g_maxbits[n]);
            const float invZ = 1.0f / g_Z[n];
            p = __expf(g_energy[n * T_ + t0 + tid] - m) * invZ;
        }
        attn[n * T_ + t0 + tid] = p;          // zeros for [cnt,128)
        ps[tid] = p;
    }
    __syncthreads();

    const float4* v4 = (const float4*)(val + ((size_t)n * T_ + t0) * D_) + d4;
    float4 acc = make_float4(0.f, 0.f, 0.f, 0.f);
    #pragma unroll 8
    for (int i = rg; i < cnt; i += 4) {       // up to 8 independent 16B loads in flight
        const float  p = ps[i];
        const float4 v = v4[(size_t)i * 64];
        acc.x += p * v.x; acc.y += p * v.y; acc.z += p * v.z; acc.w += p * v.w;
    }

    red[rg][d4] = acc;
    __syncthreads();
    if (rg == 0) {
        const float4 a = red[0][d4], b = red[1][d4], c = red[2][d4], e = red[3][d4];
        float* dst = &ctx[n * D_ + d4 * 4];
        atomicAdd(dst + 0, a.x + b.x + c.x + e.x);
        atomicAdd(dst + 1, a.y + b.y + c.y + e.y);
        atomicAdd(dst + 2, a.z + b.z + c.z + e.z);
        atomicAdd(dst + 3, a.w + b.w + c.w + e.w);
    }
}

// ---------------------------------------------------------------------------
extern "C" void kernel_launch(void* const* d_in, const int* in_sizes, int n_in,
                              void* d_out, int out_size) {
    const float* q    = (const float*)d_in[0];
    const float* key  = (const float*)d_in[1];
    const float* val  = (const float*)d_in[2];
    const int*   lens = (const int*)d_in[3];
    float* ctx  = (float*)d_out;            // first tuple element: [N, D]
    float* attn = (float*)d_out + N_ * D_;  // second tuple element: [N, T]

    k_init<<<64, 256>>>(ctx);
    k_energy<<<dim3(T_ / ETILE, N_), 256>>>(q, key, lens);
    k_combine<<<N_, 32>>>();
    k_context<<<dim3(T_ / 128, N_), 256>>>(val, lens, attn, ctx);
}

// round 6
// speedup vs baseline: 1.0991x; 1.0626x over previous
#include <cuda_runtime.h>
#include <cuda_bf16.h>
#include <math_constants.h>

#define N_ 64
#define T_ 2048
#define D_ 256
#define ETILE 64
#define NTILES (T_ / ETILE)   // 32 energy tiles per n

// Scratch (no allocs allowed)
__device__ float    g_energy[N_ * T_];
__device__ unsigned g_maxbits[N_];
__device__ float    g_Z[N_];
__device__ float    g_tml[N_ * NTILES];   // per-tile local max
__device__ float    g_tsl[N_ * NTILES];   // per-tile sum exp(e - ml)

// Order-preserving float->uint encoding (monotone for atomicMax)
__device__ __forceinline__ unsigned fenc(float f) {
    unsigned u = __float_as_uint(f);
    return (u & 0x80000000u) ? ~u : (u | 0x80000000u);
}
__device__ __forceinline__ float fdec(unsigned e) {
    return __uint_as_float((e & 0x80000000u) ? (e ^ 0x80000000u) : ~e);
}

// Robust lens decode: values are in [1, T]. If stored as int64 (little-endian),
// the high word of element 0 (int32 view index 1) is 0; if int32, it's >= 1.
__device__ __forceinline__ int get_len(const int* __restrict__ lens32, int n) {
    const bool is64 = (lens32[1] == 0);
    return is64 ? lens32[2 * n] : lens32[n];
}

// ---------------------------------------------------------------------------
// K0: zero ctx, reset maxbits and per-tile sums. Grid: 64 x 256.
// ---------------------------------------------------------------------------
__global__ void k_init(float* __restrict__ ctx) {
    const int i = blockIdx.x * blockDim.x + threadIdx.x;
    if (i < N_) g_maxbits[i] = 0u;
    if (i < N_ * NTILES) g_tsl[i] = 0.0f;
    if (i < N_ * D_) ctx[i] = 0.0f;
}

// ---------------------------------------------------------------------------
// K1: e[n,t] = <key[n,t,:], q[n,:]> for t < len; per-tile (ml, sl); one
// atomicMax per CTA. Grid (T/64, N) x 256. 8 lanes/row; all 8 K float4 loads
// issued back-to-back (MLP=8) before the dot product.
// ---------------------------------------------------------------------------
__global__ void __launch_bounds__(256, 3)
k_energy(const float* __restrict__ q,
         const float* __restrict__ key,
         const int* __restrict__ lens32) {
    const int n   = blockIdx.y;
    const int len = get_len(lens32, n);
    const int t0  = blockIdx.x * ETILE;
    if (t0 >= len) return;                    // fully-masked tile (sl stays 0)

    __shared__ float4 qs4[D_ / 4];
    __shared__ float  es[ETILE];
    const int tid = threadIdx.x;
    if (tid < 64) qs4[tid] = ((const float4*)(q + n * D_))[tid];
    __syncthreads();

    const int warp = tid >> 5, lane = tid & 31;
    const int sub  = lane >> 3;               // row within 4-row group
    const int sl   = lane & 7;                // lane within row (8 lanes/row)

    #pragma unroll
    for (int iter = 0; iter < 2; ++iter) {
        const int r = warp * 8 + iter * 4 + sub;   // row in tile [0,64)
        const int t = t0 + r;
        float s = 0.0f;
        if (t < len) {
            const float4* krow = (const float4*)(key + ((size_t)n * T_ + t) * D_);
            // issue all 8 independent loads first (explicit MLP=8)
            const float4 k0 = krow[sl +  0], k1 = krow[sl +  8];
            const float4 k2 = krow[sl + 16], k3 = krow[sl + 24];
            const float4 k4 = krow[sl + 32], k5 = krow[sl + 40];
            const float4 k6 = krow[sl + 48], k7 = krow[sl + 56];
            const float4 q0 = qs4[sl +  0], q1 = qs4[sl +  8];
            const float4 q2 = qs4[sl + 16], q3 = qs4[sl + 24];
            const float4 q4 = qs4[sl + 32], q5 = qs4[sl + 40];
            const float4 q6 = qs4[sl + 48], q7 = qs4[sl + 56];
            s = k0.x*q0.x + k0.y*q0.y + k0.z*q0.z + k0.w*q0.w
              + k1.x*q1.x + k1.y*q1.y + k1.z*q1.z + k1.w*q1.w
              + k2.x*q2.x + k2.y*q2.y + k2.z*q2.z + k2.w*q2.w
              + k3.x*q3.x + k3.y*q3.y + k3.z*q3.z + k3.w*q3.w
              + k4.x*q4.x + k4.y*q4.y + k4.z*q4.z + k4.w*q4.w
              + k5.x*q5.x + k5.y*q5.y + k5.z*q5.z + k5.w*q5.w
              + k6.x*q6.x + k6.y*q6.y + k6.z*q6.z + k6.w*q6.w
              + k7.x*q7.x + k7.y*q7.y + k7.z*q7.z + k7.w*q7.w;
        }
        s += __shfl_xor_sync(0xffffffff, s, 4);
        s += __shfl_xor_sync(0xffffffff, s, 2);
        s += __shfl_xor_sync(0xffffffff, s, 1);
        if (sl == 0) {
            if (t < len) {
                g_energy[n * T_ + t] = s;
                es[r] = s;
            } else {
                es[r] = -CUDART_INF_F;        // exp(-inf - m) == 0, safe
            }
        }
    }
    __syncthreads();

    // CTA epilogue: warp 0 reduces the 64 row-energies to (ml, sl)
    if (warp == 0) {
        const float v0 = es[lane], v1 = es[lane + 32];
        float ml = fmaxf(v0, v1);
        #pragma unroll
        for (int o = 16; o; o >>= 1)
            ml = fmaxf(ml, __shfl_xor_sync(0xffffffff, ml, o));
        float ssum = __expf(v0 - ml) + __expf(v1 - ml);
        #pragma unroll
        for (int o = 16; o; o >>= 1)
            ssum += __shfl_xor_sync(0xffffffff, ssum, o);
        if (lane == 0) {
            const int ti = n * NTILES + blockIdx.x;
            g_tml[ti] = ml;
            g_tsl[ti] = ssum;
            atomicMax(&g_maxbits[n], fenc(ml));
        }
    }
}

// ---------------------------------------------------------------------------
// K2: combine per-tile sums: Z[n] = sum_tiles sl * exp(ml - m). Grid N x 32.
// ---------------------------------------------------------------------------
__global__ void k_combine() {
    const int n    = blockIdx.x;
    const int lane = threadIdx.x;
    const float m  = fdec(g_maxbits[n]);
    const float sl = g_tsl[n * NTILES + lane];
    float c = (sl > 0.0f) ? sl * __expf(g_tml[n * NTILES + lane] - m) : 0.0f;
    #pragma unroll
    for (int o = 16; o; o >>= 1) c += __shfl_xor_sync(0xffffffff, c, o);
    if (lane == 0) g_Z[n] = c;
}

// ---------------------------------------------------------------------------
// K3: p = exp(e-m)/Z -> attn (zeros past len); ctx += p * V. 128-row tiles.
// 256 threads: d4 = tid&63 (float4 col), rg = tid>>6 (4 row groups).
// Explicit 4-deep load batches (x unroll 2 => up to 8 loads in flight).
// Grid: (T/128, N).
// ---------------------------------------------------------------------------
__global__ void __launch_bounds__(256, 3)
k_context(const float* __restrict__ val,
          const int* __restrict__ lens32,
          float* __restrict__ attn,
          float* __restrict__ ctx) {
    const int n   = blockIdx.y;
    const int len = get_len(lens32, n);
    const int t0  = blockIdx.x * 128;
    const int tid = threadIdx.x;

    if (t0 >= len) {                          // masked tile: just zero attn
        if (tid < 128) attn[n * T_ + t0 + tid] = 0.0f;
        return;
    }
    const int cnt = min(128, len - t0);
    const int d4  = tid & 63;
    const int rg  = tid >> 6;

    __shared__ float  ps[128];
    __shared__ float4 red[4][64];

    if (tid < 128) {
        float p = 0.0f;
        if (tid < cnt) {
            const float m    = fdec(g_maxbits[n]);
            const float invZ = 1.0f / g_Z[n];
            p = __expf(g_energy[n * T_ + t0 + tid] - m) * invZ;
        }
        attn[n * T_ + t0 + tid] = p;          // zeros for [cnt,128)
        ps[tid] = p;
    }
    __syncthreads();

    const float4* v4 = (const float4*)(val + ((size_t)n * T_ + t0) * D_) + d4;
    float4 acc = make_float4(0.f, 0.f, 0.f, 0.f);

    int i = rg;
    #pragma unroll 2
    for (; i + 12 < cnt; i += 16) {
        // 4 independent 16B loads issued before any use
        const float4 v0 = v4[(size_t)(i     ) * 64];
        const float4 v1 = v4[(size_t)(i +  4) * 64];
        const float4 v2 = v4[(size_t)(i +  8) * 64];
        const float4 v3 = v4[(size_t)(i + 12) * 64];
        const float p0 = ps[i], p1 = ps[i + 4], p2 = ps[i + 8], p3 = ps[i + 12];
        acc.x += p0*v0.x + p1*v1.x + p2*v2.x + p3*v3.x;
        acc.y += p0*v0.y + p1*v1.y + p2*v2.y + p3*v3.y;
        acc.z += p0*v0.z + p1*v1.z + p2*v2.z + p3*v3.z;
        acc.w += p0*v0.w + p1*v1.w + p2*v2.w + p3*v3.w;
    }
    for (; i < cnt; i += 4) {
        const float  p = ps[i];
        const float4 v = v4[(size_t)i * 64];
        acc.x += p * v.x; acc.y += p * v.y; acc.z += p * v.z; acc.w += p * v.w;
    }

    red[rg][d4] = acc;
    __syncthreads();
    if (rg == 0) {
        const float4 a = red[0][d4], b = red[1][d4], c = red[2][d4], e = red[3][d4];
        float* dst = &ctx[n * D_ + d4 * 4];
        atomicAdd(dst + 0, a.x + b.x + c.x + e.x);
        atomicAdd(dst + 1, a.y + b.y + c.y + e.y);
        atomicAdd(dst + 2, a.z + b.z + c.z + e.z);
        atomicAdd(dst + 3, a.w + b.w + c.w + e.w);
    }
}

// ---------------------------------------------------------------------------
extern "C" void kernel_launch(void* const* d_in, const int* in_sizes, int n_in,
                              void* d_out, int out_size) {
    const float* q    = (const float*)d_in[0];
    const float* key  = (const float*)d_in[1];
    const float* val  = (const float*)d_in[2];
    const int*   lens = (const int*)d_in[3];
    float* ctx  = (float*)d_out;            // first tuple element: [N, D]
    float* attn = (float*)d_out + N_ * D_;  // second tuple element: [N, T]

    k_init<<<64, 256>>>(ctx);
    k_energy<<<dim3(T_ / ETILE, N_), 256>>>(q, key, lens);
    k_combine<<<N_, 32>>>();
    k_context<<<dim3(T_ / 128, N_), 256>>>(val, lens, attn, ctx);
}

// round 7
// speedup vs baseline: 1.9193x; 1.7462x over previous
#include <cuda_runtime.h>
#include <cuda_bf16.h>
#include <math_constants.h>

#define N_ 64
#define T_ 2048
#define D_ 256
#define ETILE 64
#define NTILES (T_ / ETILE)   // 32 energy tiles per n
#define PTHRESH 1e-7f         // drop V rows with weight below this (mass <= 2e-4)

// Scratch (no allocs allowed)
__device__ float    g_energy[N_ * T_];
__device__ unsigned g_maxbits[N_];
__device__ float    g_Z[N_];
__device__ float    g_tml[N_ * NTILES];   // per-tile local max
__device__ float    g_tsl[N_ * NTILES];   // per-tile sum exp(e - ml)

// Order-preserving float->uint encoding (monotone for atomicMax)
__device__ __forceinline__ unsigned fenc(float f) {
    unsigned u = __float_as_uint(f);
    return (u & 0x80000000u) ? ~u : (u | 0x80000000u);
}
__device__ __forceinline__ float fdec(unsigned e) {
    return __uint_as_float((e & 0x80000000u) ? (e ^ 0x80000000u) : ~e);
}

// Robust lens decode: values are in [1, T]. If stored as int64 (little-endian),
// the high word of element 0 (int32 view index 1) is 0; if int32, it's >= 1.
__device__ __forceinline__ int get_len(const int* __restrict__ lens32, int n) {
    const bool is64 = (lens32[1] == 0);
    return is64 ? lens32[2 * n] : lens32[n];
}

// ---------------------------------------------------------------------------
// K0: zero ctx, reset maxbits and per-tile sums. Grid: 64 x 256.
// ---------------------------------------------------------------------------
__global__ void k_init(float* __restrict__ ctx) {
    const int i = blockIdx.x * blockDim.x + threadIdx.x;
    if (i < N_) g_maxbits[i] = 0u;
    if (i < N_ * NTILES) g_tsl[i] = 0.0f;
    if (i < N_ * D_) ctx[i] = 0.0f;
}

// ---------------------------------------------------------------------------
// K1: e[n,t] = <key[n,t,:], q[n,:]> for t < len; per-tile (ml, sl); one
// atomicMax per CTA. Grid (T/64, N) x 256. 8 lanes/row; all 8 K float4 loads
// issued back-to-back (MLP=8) before the dot product.
// ---------------------------------------------------------------------------
__global__ void __launch_bounds__(256, 3)
k_energy(const float* __restrict__ q,
         const float* __restrict__ key,
         const int* __restrict__ lens32) {
    const int n   = blockIdx.y;
    const int len = get_len(lens32, n);
    const int t0  = blockIdx.x * ETILE;
    if (t0 >= len) return;                    // fully-masked tile (sl stays 0)

    __shared__ float4 qs4[D_ / 4];
    __shared__ float  es[ETILE];
    const int tid = threadIdx.x;
    if (tid < 64) qs4[tid] = ((const float4*)(q + n * D_))[tid];
    __syncthreads();

    const int warp = tid >> 5, lane = tid & 31;
    const int sub  = lane >> 3;               // row within 4-row group
    const int sl   = lane & 7;                // lane within row (8 lanes/row)

    #pragma unroll
    for (int iter = 0; iter < 2; ++iter) {
        const int r = warp * 8 + iter * 4 + sub;   // row in tile [0,64)
        const int t = t0 + r;
        float s = 0.0f;
        if (t < len) {
            const float4* krow = (const float4*)(key + ((size_t)n * T_ + t) * D_);
            // issue all 8 independent loads first (explicit MLP=8)
            const float4 k0 = krow[sl +  0], k1 = krow[sl +  8];
            const float4 k2 = krow[sl + 16], k3 = krow[sl + 24];
            const float4 k4 = krow[sl + 32], k5 = krow[sl + 40];
            const float4 k6 = krow[sl + 48], k7 = krow[sl + 56];
            const float4 q0 = qs4[sl +  0], q1 = qs4[sl +  8];
            const float4 q2 = qs4[sl + 16], q3 = qs4[sl + 24];
            const float4 q4 = qs4[sl + 32], q5 = qs4[sl + 40];
            const float4 q6 = qs4[sl + 48], q7 = qs4[sl + 56];
            s = k0.x*q0.x + k0.y*q0.y + k0.z*q0.z + k0.w*q0.w
              + k1.x*q1.x + k1.y*q1.y + k1.z*q1.z + k1.w*q1.w
              + k2.x*q2.x + k2.y*q2.y + k2.z*q2.z + k2.w*q2.w
              + k3.x*q3.x + k3.y*q3.y + k3.z*q3.z + k3.w*q3.w
              + k4.x*q4.x + k4.y*q4.y + k4.z*q4.z + k4.w*q4.w
              + k5.x*q5.x + k5.y*q5.y + k5.z*q5.z + k5.w*q5.w
              + k6.x*q6.x + k6.y*q6.y + k6.z*q6.z + k6.w*q6.w
              + k7.x*q7.x + k7.y*q7.y + k7.z*q7.z + k7.w*q7.w;
        }
        s += __shfl_xor_sync(0xffffffff, s, 4);
        s += __shfl_xor_sync(0xffffffff, s, 2);
        s += __shfl_xor_sync(0xffffffff, s, 1);
        if (sl == 0) {
            if (t < len) {
                g_energy[n * T_ + t] = s;
                es[r] = s;
            } else {
                es[r] = -CUDART_INF_F;        // exp(-inf - m) == 0, safe
            }
        }
    }
    __syncthreads();

    // CTA epilogue: warp 0 reduces the 64 row-energies to (ml, sl)
    if (warp == 0) {
        const float v0 = es[lane], v1 = es[lane + 32];
        float ml = fmaxf(v0, v1);
        #pragma unroll
        for (int o = 16; o; o >>= 1)
            ml = fmaxf(ml, __shfl_xor_sync(0xffffffff, ml, o));
        float ssum = __expf(v0 - ml) + __expf(v1 - ml);
        #pragma unroll
        for (int o = 16; o; o >>= 1)
            ssum += __shfl_xor_sync(0xffffffff, ssum, o);
        if (lane == 0) {
            const int ti = n * NTILES + blockIdx.x;
            g_tml[ti] = ml;
            g_tsl[ti] = ssum;
            atomicMax(&g_maxbits[n], fenc(ml));
        }
    }
}

// ---------------------------------------------------------------------------
// K2: combine per-tile sums: Z[n] = sum_tiles sl * exp(ml - m). Grid N x 32.
// ---------------------------------------------------------------------------
__global__ void k_combine() {
    const int n    = blockIdx.x;
    const int lane = threadIdx.x;
    const float m  = fdec(g_maxbits[n]);
    const float sl = g_tsl[n * NTILES + lane];
    float c = (sl > 0.0f) ? sl * __expf(g_tml[n * NTILES + lane] - m) : 0.0f;
    #pragma unroll
    for (int o = 16; o; o >>= 1) c += __shfl_xor_sync(0xffffffff, c, o);
    if (lane == 0) g_Z[n] = c;
}

// ---------------------------------------------------------------------------
// K3: p = exp(e-m)/Z -> attn (zeros past len); ctx += p * V, but ONLY for
// rows with p > PTHRESH (softmax is peaked: ~a few rows per n survive).
// Survivors compacted to smem, then streamed. 128-row tiles, grid (T/128, N).
// ---------------------------------------------------------------------------
__global__ void __launch_bounds__(256, 3)
k_context(const float* __restrict__ val,
          const int* __restrict__ lens32,
          float* __restrict__ attn,
          float* __restrict__ ctx) {
    const int n   = blockIdx.y;
    const int len = get_len(lens32, n);
    const int t0  = blockIdx.x * 128;
    const int tid = threadIdx.x;

    if (t0 >= len) {                          // masked tile: just zero attn
        if (tid < 128) attn[n * T_ + t0 + tid] = 0.0f;
        return;
    }
    const int cnt = min(128, len - t0);
    const int d4  = tid & 63;
    const int rg  = tid >> 6;

    __shared__ float  ps[128];
    __shared__ float  sp[128];
    __shared__ int    sidx[128];
    __shared__ int    scnt;
    __shared__ float4 red[4][64];

    if (tid == 0) scnt = 0;
    if (tid < 128) {
        float p = 0.0f;
        if (tid < cnt) {
            const float m    = fdec(g_maxbits[n]);
            const float invZ = 1.0f / g_Z[n];
            p = __expf(g_energy[n * T_ + t0 + tid] - m) * invZ;
        }
        attn[n * T_ + t0 + tid] = p;          // zeros for [cnt,128)
        ps[tid] = p;
    }
    __syncthreads();

    // compact surviving rows (p above threshold)
    if (tid < cnt && ps[tid] > PTHRESH) {
        const int k = atomicAdd(&scnt, 1);
        sidx[k] = tid;
        sp[k]   = ps[tid];
    }
    __syncthreads();
    const int sc = scnt;
    if (sc == 0) return;

    const float4* v4 = (const float4*)(val + ((size_t)n * T_ + t0) * D_) + d4;
    float4 acc = make_float4(0.f, 0.f, 0.f, 0.f);
    #pragma unroll 4
    for (int j = rg; j < sc; j += 4) {        // independent loads across unroll
        const float  p = sp[j];
        const float4 v = v4[(size_t)sidx[j] * 64];
        acc.x += p * v.x; acc.y += p * v.y; acc.z += p * v.z; acc.w += p * v.w;
    }

    red[rg][d4] = acc;
    __syncthreads();
    if (rg == 0) {
        const float4 a = red[0][d4], b = red[1][d4], c = red[2][d4], e = red[3][d4];
        float* dst = &ctx[n * D_ + d4 * 4];
        atomicAdd(dst + 0, a.x + b.x + c.x + e.x);
        atomicAdd(dst + 1, a.y + b.y + c.y + e.y);
        atomicAdd(dst + 2, a.z + b.z + c.z + e.z);
        atomicAdd(dst + 3, a.w + b.w + c.w + e.w);
    }
}

// ---------------------------------------------------------------------------
extern "C" void kernel_launch(void* const* d_in, const int* in_sizes, int n_in,
                              void* d_out, int out_size) {
    const float* q    = (const float*)d_in[0];
    const float* key  = (const float*)d_in[1];
    const float* val  = (const float*)d_in[2];
    const int*   lens = (const int*)d_in[3];
    float* ctx  = (float*)d_out;            // first tuple element: [N, D]
    float* attn = (float*)d_out + N_ * D_;  // second tuple element: [N, T]

    k_init<<<64, 256>>>(ctx);
    k_energy<<<dim3(T_ / ETILE, N_), 256>>>(q, key, lens);
    k_combine<<<N_, 32>>>();
    k_context<<<dim3(T_ / 128, N_), 256>>>(val, lens, attn, ctx);
}

// round 8
// speedup vs baseline: 1.9323x; 1.0068x over previous
#include <cuda_runtime.h>
#include <cuda_bf16.h>
#include <math_constants.h>

#define N_ 64
#define T_ 2048
#define D_ 256
#define ETILE 64
#define NTILES (T_ / ETILE)   // 32 energy tiles per n
#define CTILE 256             // context tile rows
#define PTHRESH 1e-7f         // drop V rows below this weight (mass <= 2e-4)

// Scratch (no allocs allowed)
__device__ float g_energy[N_ * T_];
__device__ float g_M[N_];
__device__ float g_Z[N_];
__device__ float g_tml[N_ * NTILES];   // per-tile local max
__device__ float g_tsl[N_ * NTILES];   // per-tile sum exp(e - ml)

// Robust lens decode: values are in [1, T]. If stored as int64 (little-endian),
// the high word of element 0 (int32 view index 1) is 0; if int32, it's >= 1.
__device__ __forceinline__ int get_len(const int* __restrict__ lens32, int n) {
    const bool is64 = (lens32[1] == 0);
    return is64 ? lens32[2 * n] : lens32[n];
}

// ---------------------------------------------------------------------------
// K0: zero ctx (atomicAdd target). Grid: 64 x 256 covers N*D = 16384.
// ---------------------------------------------------------------------------
__global__ void k_init(float* __restrict__ ctx) {
    const int i = blockIdx.x * blockDim.x + threadIdx.x;
    if (i < N_ * D_) ctx[i] = 0.0f;
}

// ---------------------------------------------------------------------------
// K1: e[n,t] = <key[n,t,:], q[n,:]> for t < len; per-tile (ml, sl).
// Grid (T/64, N) x 256. 8 lanes/row; 8 K float4 loads in flight per lane.
// No global atomics.
// ---------------------------------------------------------------------------
__global__ void __launch_bounds__(256, 3)
k_energy(const float* __restrict__ q,
         const float* __restrict__ key,
         const int* __restrict__ lens32) {
    const int n   = blockIdx.y;
    const int len = get_len(lens32, n);
    const int t0  = blockIdx.x * ETILE;
    if (t0 >= len) return;                    // fully-masked tile (combine skips it)

    __shared__ float4 qs4[D_ / 4];
    __shared__ float  es[ETILE];
    const int tid = threadIdx.x;
    if (tid < 64) qs4[tid] = ((const float4*)(q + n * D_))[tid];
    __syncthreads();

    const int warp = tid >> 5, lane = tid & 31;
    const int sub  = lane >> 3;               // row within 4-row group
    const int sl   = lane & 7;                // lane within row (8 lanes/row)

    #pragma unroll
    for (int iter = 0; iter < 2; ++iter) {
        const int r = warp * 8 + iter * 4 + sub;   // row in tile [0,64)
        const int t = t0 + r;
        float s = 0.0f;
        if (t < len) {
            const float4* krow = (const float4*)(key + ((size_t)n * T_ + t) * D_);
            // issue all 8 independent loads first (explicit MLP=8)
            const float4 k0 = krow[sl +  0], k1 = krow[sl +  8];
            const float4 k2 = krow[sl + 16], k3 = krow[sl + 24];
            const float4 k4 = krow[sl + 32], k5 = krow[sl + 40];
            const float4 k6 = krow[sl + 48], k7 = krow[sl + 56];
            const float4 q0 = qs4[sl +  0], q1 = qs4[sl +  8];
            const float4 q2 = qs4[sl + 16], q3 = qs4[sl + 24];
            const float4 q4 = qs4[sl + 32], q5 = qs4[sl + 40];
            const float4 q6 = qs4[sl + 48], q7 = qs4[sl + 56];
            s = k0.x*q0.x + k0.y*q0.y + k0.z*q0.z + k0.w*q0.w
              + k1.x*q1.x + k1.y*q1.y + k1.z*q1.z + k1.w*q1.w
              + k2.x*q2.x + k2.y*q2.y + k2.z*q2.z + k2.w*q2.w
              + k3.x*q3.x + k3.y*q3.y + k3.z*q3.z + k3.w*q3.w
              + k4.x*q4.x + k4.y*q4.y + k4.z*q4.z + k4.w*q4.w
              + k5.x*q5.x + k5.y*q5.y + k5.z*q5.z + k5.w*q5.w
              + k6.x*q6.x + k6.y*q6.y + k6.z*q6.z + k6.w*q6.w
              + k7.x*q7.x + k7.y*q7.y + k7.z*q7.z + k7.w*q7.w;
        }
        s += __shfl_xor_sync(0xffffffff, s, 4);
        s += __shfl_xor_sync(0xffffffff, s, 2);
        s += __shfl_xor_sync(0xffffffff, s, 1);
        if (sl == 0) {
            if (t < len) {
                g_energy[n * T_ + t] = s;
                es[r] = s;
            } else {
                es[r] = -CUDART_INF_F;        // exp(-inf - ml) == 0, safe
            }
        }
    }
    __syncthreads();

    // CTA epilogue: warp 0 reduces the 64 row-energies to (ml, sl)
    if (warp == 0) {
        const float v0 = es[lane], v1 = es[lane + 32];
        float ml = fmaxf(v0, v1);
        #pragma unroll
        for (int o = 16; o; o >>= 1)
            ml = fmaxf(ml, __shfl_xor_sync(0xffffffff, ml, o));
        float ssum = __expf(v0 - ml) + __expf(v1 - ml);
        #pragma unroll
        for (int o = 16; o; o >>= 1)
            ssum += __shfl_xor_sync(0xffffffff, ssum, o);
        if (lane == 0) {
            const int ti = n * NTILES + blockIdx.x;
            g_tml[ti] = ml;
            g_tsl[ti] = ssum;
        }
    }
}

// ---------------------------------------------------------------------------
// K2: m = max over valid tiles of tml; Z = sum sl * exp(ml - m). Grid N x 32.
// (lane ti owns tile ti; tile valid iff ti*ETILE < len)
// ---------------------------------------------------------------------------
__global__ void k_combine(const int* __restrict__ lens32) {
    const int n    = blockIdx.x;
    const int len  = get_len(lens32, n);
    const int lane = threadIdx.x;
    const bool valid = (lane * ETILE) < len;

    const float ml = valid ? g_tml[n * NTILES + lane] : -CUDART_INF_F;
    const float sl = valid ? g_tsl[n * NTILES + lane] : 0.0f;

    float m = ml;
    #pragma unroll
    for (int o = 16; o; o >>= 1)
        m = fmaxf(m, __shfl_xor_sync(0xffffffff, m, o));

    float c = valid ? sl * __expf(ml - m) : 0.0f;
    #pragma unroll
    for (int o = 16; o; o >>= 1) c += __shfl_xor_sync(0xffffffff, c, o);

    if (lane == 0) { g_M[n] = m; g_Z[n] = c; }
}

// ---------------------------------------------------------------------------
// K3: p = exp(e-m)/Z -> attn (zeros past len); ctx += p*V for rows with
// p > PTHRESH. Ballot-based compaction (no smem atomic chain).
// Grid (T/256, N) x 256, thread-per-t.
// ---------------------------------------------------------------------------
__global__ void __launch_bounds__(256, 3)
k_context(const float* __restrict__ val,
          const int* __restrict__ lens32,
          float* __restrict__ attn,
          float* __restrict__ ctx) {
    const int n   = blockIdx.y;
    const int len = get_len(lens32, n);
    const int t0  = blockIdx.x * CTILE;
    const int tid = threadIdx.x;

    if (t0 >= len) {                          // masked tile: just zero attn
        attn[n * T_ + t0 + tid] = 0.0f;
        return;
    }

    __shared__ float    sp[CTILE];
    __shared__ int      sidx[CTILE];
    __shared__ int      wbase[9];             // warp offsets (exclusive scan)
    __shared__ float4   red[4][64];

    // p for this thread's t
    const int t = t0 + tid;
    float p = 0.0f;
    if (t < len) {
        const float m    = g_M[n];
        const float invZ = 1.0f / g_Z[n];
        p = __expf(g_energy[n * T_ + t] - m) * invZ;
    }
    attn[n * T_ + t] = p;                     // zeros past len

    // ballot compaction of survivors
    const int warp = tid >> 5, lane = tid & 31;
    const bool live = (p > PTHRESH);
    const unsigned bal = __ballot_sync(0xffffffff, live);
    if (lane == 0) wbase[warp] = __popc(bal);
    __syncthreads();
    if (tid == 0) {
        int run = 0;
        #pragma unroll
        for (int w = 0; w < 8; ++w) { const int c = wbase[w]; wbase[w] = run; run += c; }
        wbase[8] = run;
    }
    __syncthreads();
    if (live) {
        const int k = wbase[warp] + __popc(bal & ((1u << lane) - 1u));
        sidx[k] = tid;
        sp[k]   = p;
    }
    __syncthreads();
    const int sc = wbase[8];
    if (sc == 0) return;

    // stream surviving V rows: 64 float4 columns x 4 row groups
    const int d4 = tid & 63;
    const int rg = tid >> 6;
    const float4* v4 = (const float4*)(val + ((size_t)n * T_ + t0) * D_) + d4;
    float4 acc = make_float4(0.f, 0.f, 0.f, 0.f);
    #pragma unroll 4
    for (int j = rg; j < sc; j += 4) {
        const float  pw = sp[j];
        const float4 v  = v4[(size_t)sidx[j] * 64];
        acc.x += pw * v.x; acc.y += pw * v.y; acc.z += pw * v.z; acc.w += pw * v.w;
    }

    red[rg][d4] = acc;
    __syncthreads();
    if (rg == 0) {
        const float4 a = red[0][d4], b = red[1][d4], c = red[2][d4], e = red[3][d4];
        float* dst = &ctx[n * D_ + d4 * 4];
        atomicAdd(dst + 0, a.x + b.x + c.x + e.x);
        atomicAdd(dst + 1, a.y + b.y + c.y + e.y);
        atomicAdd(dst + 2, a.z + b.z + c.z + e.z);
        atomicAdd(dst + 3, a.w + b.w + c.w + e.w);
    }
}

// ---------------------------------------------------------------------------
extern "C" void kernel_launch(void* const* d_in, const int* in_sizes, int n_in,
                              void* d_out, int out_size) {
    const float* q    = (const float*)d_in[0];
    const float* key  = (const float*)d_in[1];
    const float* val  = (const float*)d_in[2];
    const int*   lens = (const int*)d_in[3];
    float* ctx  = (float*)d_out;            // first tuple element: [N, D]
    float* attn = (float*)d_out + N_ * D_;  // second tuple element: [N, T]

    k_init<<<64, 256>>>(ctx);
    k_energy<<<dim3(T_ / ETILE, N_), 256>>>(q, key, lens);
    k_combine<<<N_, 32>>>(lens);
    k_context<<<dim3(T_ / CTILE, N_), 256>>>(val, lens, attn, ctx);
}

// round 9
// speedup vs baseline: 1.9488x; 1.0085x over previous
#include <cuda_runtime.h>
#include <cuda_bf16.h>
#include <math_constants.h>

#define N_ 64
#define T_ 2048
#define D_ 256
#define ETILE 64
#define NTILES (T_ / ETILE)    // 32 energy tiles per n (== warp size)
#define PTHRESH 1e-7f          // drop V rows below this weight (mass <= 2e-4)
#define CAND_DELTA 16.2f       // ln(1e7) = 16.12: e <= ml_tile - 16.2 => p < 1e-7

// Scratch (no allocs allowed). All deterministic, no init kernel needed:
// only slots belonging to valid tiles (t0 < len) are ever read, and those
// are always written by k_energy on every call.
__device__ __align__(16) float g_energy[N_ * T_];
__device__ float g_tml[N_ * NTILES];       // per-tile local max
__device__ float g_tsl[N_ * NTILES];       // per-tile sum exp(e - ml)
__device__ int   g_tcc[N_ * NTILES];       // per-tile candidate count
__device__ int   g_candt[N_ * T_];         // candidate t (global), per-tile slots
__device__ float g_cande[N_ * T_];         // candidate energy

// Robust lens decode: values are in [1, T]. If stored as int64 (little-endian),
// the high word of element 0 (int32 view index 1) is 0; if int32, it's >= 1.
__device__ __forceinline__ int get_len(const int* __restrict__ lens32, int n) {
    const bool is64 = (lens32[1] == 0);
    return is64 ? lens32[2 * n] : lens32[n];
}

// ---------------------------------------------------------------------------
// K1: e[n,t] = <key[n,t,:], q[n,:]> for t < len; per-tile (ml, sl) + inline
// candidate recording (rows with e > ml - CAND_DELTA) into fixed slots.
// Grid (T/64, N) x 256. 8 lanes/row; 8 K float4 loads in flight per lane.
// ---------------------------------------------------------------------------
__global__ void __launch_bounds__(256, 3)
k_energy(const float* __restrict__ q,
         const float* __restrict__ key,
         const int* __restrict__ lens32) {
    const int n   = blockIdx.y;
    const int len = get_len(lens32, n);
    const int t0  = blockIdx.x * ETILE;
    if (t0 >= len) return;                    // invalid tile: never read downstream

    __shared__ float4 qs4[D_ / 4];
    __shared__ float  es[ETILE];
    const int tid = threadIdx.x;
    if (tid < 64) qs4[tid] = ((const float4*)(q + n * D_))[tid];
    __syncthreads();

    const int warp = tid >> 5, lane = tid & 31;
    const int sub  = lane >> 3;               // row within 4-row group
    const int sl   = lane & 7;                // lane within row (8 lanes/row)

    #pragma unroll
    for (int iter = 0; iter < 2; ++iter) {
        const int r = warp * 8 + iter * 4 + sub;   // row in tile [0,64)
        const int t = t0 + r;
        float s = 0.0f;
        if (t < len) {
            const float4* krow = (const float4*)(key + ((size_t)n * T_ + t) * D_);
            // issue all 8 independent loads first (explicit MLP=8)
            const float4 k0 = krow[sl +  0], k1 = krow[sl +  8];
            const float4 k2 = krow[sl + 16], k3 = krow[sl + 24];
            const float4 k4 = krow[sl + 32], k5 = krow[sl + 40];
            const float4 k6 = krow[sl + 48], k7 = krow[sl + 56];
            const float4 q0 = qs4[sl +  0], q1 = qs4[sl +  8];
            const float4 q2 = qs4[sl + 16], q3 = qs4[sl + 24];
            const float4 q4 = qs4[sl + 32], q5 = qs4[sl + 40];
            const float4 q6 = qs4[sl + 48], q7 = qs4[sl + 56];
            s = k0.x*q0.x + k0.y*q0.y + k0.z*q0.z + k0.w*q0.w
              + k1.x*q1.x + k1.y*q1.y + k1.z*q1.z + k1.w*q1.w
              + k2.x*q2.x + k2.y*q2.y + k2.z*q2.z + k2.w*q2.w
              + k3.x*q3.x + k3.y*q3.y + k3.z*q3.z + k3.w*q3.w
              + k4.x*q4.x + k4.y*q4.y + k4.z*q4.z + k4.w*q4.w
              + k5.x*q5.x + k5.y*q5.y + k5.z*q5.z + k5.w*q5.w
              + k6.x*q6.x + k6.y*q6.y + k6.z*q6.z + k6.w*q6.w
              + k7.x*q7.x + k7.y*q7.y + k7.z*q7.z + k7.w*q7.w;
        }
        s += __shfl_xor_sync(0xffffffff, s, 4);
        s += __shfl_xor_sync(0xffffffff, s, 2);
        s += __shfl_xor_sync(0xffffffff, s, 1);
        if (sl == 0) {
            if (t < len) {
                g_energy[n * T_ + t] = s;
                es[r] = s;
            } else {
                es[r] = -CUDART_INF_F;        // never a max / candidate
            }
        }
    }
    __syncthreads();

    // CTA epilogue (warp 0): (ml, sl) + ordered candidate push into tile slots
    if (warp == 0) {
        const float v0 = es[lane], v1 = es[lane + 32];
        float ml = fmaxf(v0, v1);
        #pragma unroll
        for (int o = 16; o; o >>= 1)
            ml = fmaxf(ml, __shfl_xor_sync(0xffffffff, ml, o));
        float ssum = __expf(v0 - ml) + __expf(v1 - ml);
        #pragma unroll
        for (int o = 16; o; o >>= 1)
            ssum += __shfl_xor_sync(0xffffffff, ssum, o);

        const float thr = ml - CAND_DELTA;
        const bool l0 = (v0 > thr), l1 = (v1 > thr);   // -inf rows auto-fail
        const unsigned b0 = __ballot_sync(0xffffffff, l0);
        const unsigned b1 = __ballot_sync(0xffffffff, l1);
        const unsigned ltm = (1u << lane) - 1u;
        const int ti   = n * NTILES + blockIdx.x;
        const int base = ti * ETILE;
        if (l0) {
            const int k = __popc(b0 & ltm);
            g_candt[base + k] = t0 + lane;
            g_cande[base + k] = v0;
        }
        const int c0 = __popc(b0);
        if (l1) {
            const int k = c0 + __popc(b1 & ltm);
            g_candt[base + k] = t0 + lane + 32;
            g_cande[base + k] = v1;
        }
        if (lane == 0) {
            g_tml[ti] = ml;
            g_tsl[ti] = ssum;
            g_tcc[ti] = c0 + __popc(b1);
        }
    }
}

// ---------------------------------------------------------------------------
// K2: finish. Grid (3, N) x 256. Every CTA recomputes (m, Z) from the 32 tile
// summaries. bx<2: float4-streaming attn write (1024 t's per CTA).
// bx==2: order-preserving compaction of candidates -> exact p>PTHRESH filter
// -> V gather -> direct ctx store. No atomics anywhere.
// ---------------------------------------------------------------------------
__global__ void __launch_bounds__(256, 3)
k_finish(const float* __restrict__ val,
         const int* __restrict__ lens32,
         float* __restrict__ attn,
         float* __restrict__ ctx) {
    const int n   = blockIdx.y;
    const int len = get_len(lens32, n);
    const int tid = threadIdx.x;
    const int warp = tid >> 5, lane = tid & 31;

    __shared__ float sM, sInvZ;
    if (warp == 0) {                          // m, Z from valid tile summaries
        const bool valid = (lane * ETILE) < len;
        const float ml = valid ? g_tml[n * NTILES + lane] : -CUDART_INF_F;
        const float sl = valid ? g_tsl[n * NTILES + lane] : 0.0f;
        float m = ml;
        #pragma unroll
        for (int o = 16; o; o >>= 1)
            m = fmaxf(m, __shfl_xor_sync(0xffffffff, m, o));
        float c = valid ? sl * __expf(ml - m) : 0.0f;
        #pragma unroll
        for (int o = 16; o; o >>= 1) c += __shfl_xor_sync(0xffffffff, c, o);
        if (lane == 0) { sM = m; sInvZ = 1.0f / c; }
    }
    __syncthreads();
    const float m = sM, invZ = sInvZ;

    if (blockIdx.x < 2) {                     // -------- attn streaming --------
        const int t0 = blockIdx.x * 1024 + tid * 4;
        const float4 e4 = *(const float4*)&g_energy[n * T_ + t0];
        float4 p;
        p.x = (t0 + 0 < len) ? __expf(e4.x - m) * invZ : 0.0f;
        p.y = (t0 + 1 < len) ? __expf(e4.y - m) * invZ : 0.0f;
        p.z = (t0 + 2 < len) ? __expf(e4.z - m) * invZ : 0.0f;
        p.w = (t0 + 3 < len) ? __expf(e4.w - m) * invZ : 0.0f;
        *(float4*)&attn[n * T_ + t0] = p;
        return;
    }

    // ------------------------------- ctx -----------------------------------
    __shared__ int    stcc[NTILES];
    __shared__ int    wtot[9];
    __shared__ int    sidx[T_];
    __shared__ float  sp[T_];
    __shared__ float4 red[4][64];

    if (tid < NTILES)
        stcc[tid] = ((tid * ETILE) < len) ? g_tcc[n * NTILES + tid] : 0;
    __syncthreads();

    // each thread owns 8 contiguous candidate slots; order-preserving compact
    int   tk[8];
    float pk[8];
    unsigned livem = 0;
    int cnt = 0;
    #pragma unroll
    for (int k = 0; k < 8; ++k) {
        const int s    = tid * 8 + k;
        const int tile = s >> 6, slot = s & 63;
        bool live = (slot < stcc[tile]);
        float p = 0.0f;
        if (live) {
            const int idx = (n * NTILES + tile) * ETILE + slot;
            p = __expf(g_cande[idx] - m) * invZ;
            tk[k] = g_candt[idx];
            live = (p > PTHRESH);
        }
        pk[k] = p;
        if (live) { livem |= (1u << k); ++cnt; }
    }
    // exclusive scan of counts over 256 threads
    int inc = cnt;
    #pragma unroll
    for (int o = 1; o < 32; o <<= 1) {
        const int v = __shfl_up_sync(0xffffffff, inc, o);
        if (lane >= o) inc += v;
    }
    if (lane == 31) wtot[warp] = inc;
    __syncthreads();
    if (tid == 0) {
        int run = 0;
        #pragma unroll
        for (int w = 0; w < 8; ++w) { const int c = wtot[w]; wtot[w] = run; run += c; }
        wtot[8] = run;
    }
    __syncthreads();
    int off = wtot[warp] + inc - cnt;
    #pragma unroll
    for (int k = 0; k < 8; ++k) {
        if ((livem >> k) & 1u) { sidx[off] = tk[k]; sp[off] = pk[k]; ++off; }
    }
    __syncthreads();
    const int sc = wtot[8];                   // >= 1 always (max row has p = 1/Z)

    // gather surviving V rows: 64 float4 columns x 4 row groups
    const int d4 = tid & 63;
    const int rg = tid >> 6;
    const float4* v4 = (const float4*)(val + (size_t)n * T_ * D_) + d4;
    float4 acc = make_float4(0.f, 0.f, 0.f, 0.f);
    #pragma unroll 4
    for (int j = rg; j < sc; j += 4) {
        const float  pw = sp[j];
        const float4 v  = v4[(size_t)sidx[j] * 64];
        acc.x += pw * v.x; acc.y += pw * v.y; acc.z += pw * v.z; acc.w += pw * v.w;
    }
    red[rg][d4] = acc;
    __syncthreads();
    if (rg == 0) {
        const float4 a = red[0][d4], b = red[1][d4], c = red[2][d4], e = red[3][d4];
        float4 out;
        out.x = a.x + b.x + c.x + e.x;
        out.y = a.y + b.y + c.y + e.y;
        out.z = a.z + b.z + c.z + e.z;
        out.w = a.w + b.w + c.w + e.w;
        *(float4*)&ctx[n * D_ + d4 * 4] = out;   // direct store, no init/atomics
    }
}

// ---------------------------------------------------------------------------
extern "C" void kernel_launch(void* const* d_in, const int* in_sizes, int n_in,
                              void* d_out, int out_size) {
    const float* q    = (const float*)d_in[0];
    const float* key  = (const float*)d_in[1];
    const float* val  = (const float*)d_in[2];
    const int*   lens = (const int*)d_in[3];
    float* ctx  = (float*)d_out;            // first tuple element: [N, D]
    float* attn = (float*)d_out + N_ * D_;  // second tuple element: [N, T]

    k_energy<<<dim3(T_ / ETILE, N_), 256>>>(q, key, lens);
    k_finish<<<dim3(3, N_), 256>>>(val, lens, attn, ctx);
}